// round 12
// baseline (speedup 1.0000x reference)
#include <cuda_runtime.h>
#include <math.h>

// Problem constants
#define T_STEPS 256
#define B_SZ    512
#define D_SZ    512
#define H_SZ    512
#define NQ      8
#define NCOLS   (4 * H_SZ + NQ)   // 2056 real columns
#define NP      2176              // padded to multiple of 128
#define ALPHA   0.7f

// ---------------------------------------------------------------------------
// Device scratch (static; no runtime allocation allowed)
// ---------------------------------------------------------------------------
__device__ float g_Zx[(size_t)T_STEPS * B_SZ * NP];  // x-projection for all (t,b): ~1.14 GB
__device__ float g_Z[(size_t)B_SZ * NP];             // per-step pre-activation buffer
__device__ float g_hx[B_SZ * H_SZ];
__device__ float g_cx[B_SZ * H_SZ];
__device__ float g_Wxcat[(size_t)D_SZ * NP];         // packed x-half weights (512 x NP)
__device__ float g_Whcat[(size_t)H_SZ * NP];         // packed h-half weights (512 x NP)

// ---------------------------------------------------------------------------
// Utility kernels
// ---------------------------------------------------------------------------
__global__ void zero_state_kernel() {
    int i = blockIdx.x * blockDim.x + threadIdx.x;
    if (i < B_SZ * H_SZ) { g_hx[i] = 0.0f; g_cx[i] = 0.0f; }
}

// Pack [Wf | Wi | Wu | Wo | Wq | zero-pad] for both the x rows (0..D-1) and
// the h rows (D..D+H-1) of the original (IN, out) row-major weights.
__global__ void pack_weights_kernel(const float* __restrict__ Wf,
                                    const float* __restrict__ Wi,
                                    const float* __restrict__ Wu,
                                    const float* __restrict__ Wo,
                                    const float* __restrict__ Wq) {
    int idx = blockIdx.x * blockDim.x + threadIdx.x;
    const int total = 2 * D_SZ * NP;
    if (idx >= total) return;
    int which = idx / (D_SZ * NP);     // 0 = x-half, 1 = h-half
    int rem   = idx % (D_SZ * NP);
    int k = rem / NP;
    int n = rem % NP;
    int row = which ? (D_SZ + k) : k;  // row in the original (IN=1024) dimension
    float v = 0.0f;
    if (n < 4 * H_SZ) {
        int g = n >> 9;          // /512
        int h = n & (H_SZ - 1);
        const float* W = (g == 0) ? Wf : (g == 1) ? Wi : (g == 2) ? Wu : Wo;
        v = W[(size_t)row * H_SZ + h];
    } else if (n < NCOLS) {
        v = Wq[(size_t)row * NQ + (n - 4 * H_SZ)];
    }
    if (which) g_Whcat[(size_t)k * NP + n] = v;
    else       g_Wxcat[(size_t)k * NP + n] = v;
}

// ---------------------------------------------------------------------------
// Tiled fp32 SGEMM.
// MODE 0: g_Zx[m, :] = A(inputs)[m, :512] @ g_Wxcat          (M = T*B)
// MODE 1: g_Z [m, :] = g_hx[m, :512] @ g_Whcat + g_Zx[t*B+m] (M = B)
// lda = 512 in both modes. N = NP, K = 512. No bounds checks (exact tiling).
// Threads = (BM/TM)*(BN/TN) = 256.
// ---------------------------------------------------------------------------
template <int BM, int BN, int BK, int TM, int TN, int MODE>
__global__ __launch_bounds__(256) void sgemm_kernel(const float* __restrict__ Ain, int t) {
    __shared__ float As[BK][BM];
    __shared__ float Bs[BK][BN];

    const float* __restrict__ A  = (MODE == 0) ? Ain : g_hx;
    const float* __restrict__ Bm = (MODE == 0) ? g_Wxcat : g_Whcat;

    const int tid  = threadIdx.x;
    const int NT   = (BM / TM) * (BN / TN);   // 256
    const int tcol = tid % (BN / TN);
    const int trow = tid / (BN / TN);
    const int m0 = blockIdx.y * BM;
    const int n0 = blockIdx.x * BN;

    float acc[TM][TN];
#pragma unroll
    for (int i = 0; i < TM; i++)
#pragma unroll
        for (int j = 0; j < TN; j++) acc[i][j] = 0.0f;

    const int K = 512;
    for (int k0 = 0; k0 < K; k0 += BK) {
        // Load A tile (BM x BK), store transposed into As[k][m]
#pragma unroll
        for (int i = tid; i < BM * BK / 4; i += NT) {
            int r  = i / (BK / 4);
            int c4 = i % (BK / 4);
            float4 v = *reinterpret_cast<const float4*>(
                &A[(size_t)(m0 + r) * 512 + k0 + c4 * 4]);
            As[c4 * 4 + 0][r] = v.x;
            As[c4 * 4 + 1][r] = v.y;
            As[c4 * 4 + 2][r] = v.z;
            As[c4 * 4 + 3][r] = v.w;
        }
        // Load B tile (BK x BN) row-major
#pragma unroll
        for (int i = tid; i < BK * BN / 4; i += NT) {
            int r  = i / (BN / 4);
            int c4 = i % (BN / 4);
            *reinterpret_cast<float4*>(&Bs[r][c4 * 4]) =
                *reinterpret_cast<const float4*>(&Bm[(size_t)(k0 + r) * NP + n0 + c4 * 4]);
        }
        __syncthreads();

#pragma unroll
        for (int kk = 0; kk < BK; kk++) {
            float a[TM], b[TN];
#pragma unroll
            for (int i = 0; i < TM; i += 4) {
                float4 v = *reinterpret_cast<const float4*>(&As[kk][trow * TM + i]);
                a[i] = v.x; a[i + 1] = v.y; a[i + 2] = v.z; a[i + 3] = v.w;
            }
#pragma unroll
            for (int j = 0; j < TN; j += 4) {
                float4 v = *reinterpret_cast<const float4*>(&Bs[kk][tcol * TN + j]);
                b[j] = v.x; b[j + 1] = v.y; b[j + 2] = v.z; b[j + 3] = v.w;
            }
#pragma unroll
            for (int i = 0; i < TM; i++)
#pragma unroll
                for (int j = 0; j < TN; j++)
                    acc[i][j] = fmaf(a[i], b[j], acc[i][j]);
        }
        __syncthreads();
    }

    // Epilogue
#pragma unroll
    for (int i = 0; i < TM; i++) {
        int m = m0 + trow * TM + i;
#pragma unroll
        for (int j = 0; j < TN; j += 4) {
            size_t off = (size_t)m * NP + n0 + tcol * TN + j;
            float4 v;
            v.x = acc[i][j]; v.y = acc[i][j + 1]; v.z = acc[i][j + 2]; v.w = acc[i][j + 3];
            if (MODE == 0) {
                *reinterpret_cast<float4*>(&g_Zx[off]) = v;
            } else {
                float4 ad = *reinterpret_cast<const float4*>(
                    &g_Zx[(size_t)(t * B_SZ) * NP + off]);
                v.x += ad.x; v.y += ad.y; v.z += ad.z; v.w += ad.w;
                *reinterpret_cast<float4*>(&g_Z[off]) = v;
            }
        }
    }
}

// ---------------------------------------------------------------------------
// Per-step fused update: quantum feature map + 8->512 matvec + gates + state.
// grid = (H/256, B), block = 256.
// ---------------------------------------------------------------------------
__device__ __forceinline__ float sigm(float x) { return 1.0f / (1.0f + expf(-x)); }

__global__ __launch_bounds__(256) void step_update_kernel(
    const float* __restrict__ bf, const float* __restrict__ bi,
    const float* __restrict__ bu, const float* __restrict__ bo,
    const float* __restrict__ bq, const float* __restrict__ Wqh,
    const float* __restrict__ bqh,
    const float* __restrict__ th_f, const float* __restrict__ th_i,
    const float* __restrict__ th_u, const float* __restrict__ th_o,
    float* __restrict__ out, int t) {
    const int b = blockIdx.y;
    const int h = blockIdx.x * blockDim.x + threadIdx.x;
    const size_t zb = (size_t)b * NP;

    // q_in (8 values, broadcast across the block)
    float q[NQ];
#pragma unroll
    for (int j = 0; j < NQ; j++) q[j] = g_Z[zb + 4 * H_SZ + j] + bq[j];

    // cumprod-of-cos feature maps and their 8->H projection (fused)
    float ef = 1.0f, ei = 1.0f, eu = 1.0f, eo = 1.0f;
    float qb = bqh[h];
    float sf = qb, si = qb, su = qb, so = qb;
#pragma unroll
    for (int j = 0; j < NQ; j++) {
        ef *= cosf(q[j] + th_f[j]);
        ei *= cosf(q[j] + th_i[j]);
        eu *= cosf(q[j] + th_u[j]);
        eo *= cosf(q[j] + th_o[j]);
        float w = Wqh[j * H_SZ + h];
        sf = fmaf(ef, w, sf);
        si = fmaf(ei, w, si);
        su = fmaf(eu, w, su);
        so = fmaf(eo, w, so);
    }

    float zf = g_Z[zb + 0 * H_SZ + h] + bf[h];
    float zi = g_Z[zb + 1 * H_SZ + h] + bi[h];
    float zu = g_Z[zb + 2 * H_SZ + h] + bu[h];
    float zo = g_Z[zb + 3 * H_SZ + h] + bo[h];

    float f = ALPHA * sigm(zf) + (1.0f - ALPHA) * sigm(sf);
    float i_ = ALPHA * sigm(zi) + (1.0f - ALPHA) * sigm(si);
    float g = ALPHA * tanhf(zu) + (1.0f - ALPHA) * tanhf(su);
    float o = ALPHA * sigm(zo) + (1.0f - ALPHA) * sigm(so);

    int idx = b * H_SZ + h;
    float c = f * g_cx[idx] + i_ * g;
    float hx = o * tanhf(c);
    g_cx[idx] = c;
    g_hx[idx] = hx;
    out[(size_t)t * B_SZ * H_SZ + idx] = hx;
}

// Write final (hx, cx) to the tail of d_out if the flattened output includes them.
__global__ void write_tail_kernel(float* __restrict__ dst, int count) {
    int i = blockIdx.x * blockDim.x + threadIdx.x;
    if (i < count) {
        dst[i] = (i < B_SZ * H_SZ) ? g_hx[i] : g_cx[i - B_SZ * H_SZ];
    }
}

// ---------------------------------------------------------------------------
// Launch
// ---------------------------------------------------------------------------
extern "C" void kernel_launch(void* const* d_in, const int* in_sizes, int n_in,
                              void* d_out, int out_size) {
    const float* inputs = (const float*)d_in[0];
    const float* Wf = (const float*)d_in[1];  const float* bf = (const float*)d_in[2];
    const float* Wi = (const float*)d_in[3];  const float* bi = (const float*)d_in[4];
    const float* Wu = (const float*)d_in[5];  const float* bu = (const float*)d_in[6];
    const float* Wo = (const float*)d_in[7];  const float* bo = (const float*)d_in[8];
    const float* Wq = (const float*)d_in[9];  const float* bq = (const float*)d_in[10];
    const float* Wqh = (const float*)d_in[11]; const float* bqh = (const float*)d_in[12];
    const float* thf = (const float*)d_in[13]; const float* thi = (const float*)d_in[14];
    const float* thu = (const float*)d_in[15]; const float* tho = (const float*)d_in[16];
    float* out = (float*)d_out;

    // Init state + pack weights (cheap, runs every call for determinism)
    zero_state_kernel<<<(B_SZ * H_SZ + 255) / 256, 256>>>();
    pack_weights_kernel<<<(2 * D_SZ * NP + 255) / 256, 256>>>(Wf, Wi, Wu, Wo, Wq);

    // Precompute x-projection for all timesteps: (T*B, 512) @ (512, NP)
    sgemm_kernel<128, 128, 16, 8, 8, 0>
        <<<dim3(NP / 128, (T_STEPS * B_SZ) / 128), 256>>>(inputs, 0);

    // Sequential recurrence
    for (int t = 0; t < T_STEPS; t++) {
        sgemm_kernel<64, 128, 16, 4, 8, 1>
            <<<dim3(NP / 128, B_SZ / 64), 256>>>(nullptr, t);
        step_update_kernel<<<dim3(H_SZ / 256, B_SZ), 256>>>(
            bf, bi, bu, bo, bq, Wqh, bqh, thf, thi, thu, tho, out, t);
    }

    // Optional tail: final (hx, cx) after the main (T,B,H) output
    long long mainN = (long long)T_STEPS * B_SZ * H_SZ;
    if ((long long)out_size > mainN) {
        long long rem = (long long)out_size - mainN;
        long long cap = (long long)2 * B_SZ * H_SZ;
        int cnt = (int)(rem < cap ? rem : cap);
        write_tail_kernel<<<(cnt + 255) / 256, 256>>>(out + mainN, cnt);
    }
}

// round 13
// speedup vs baseline: 1.0024x; 1.0024x over previous
#include <cuda_runtime.h>
#include <math.h>

// Problem constants
#define T_STEPS 256
#define B_SZ    512
#define D_SZ    512
#define H_SZ    512
#define NQ      8
#define NCOLS   (4 * H_SZ + NQ)   // 2056 real columns
#define NP      2176              // padded to multiple of 128
#define ALPHA   0.7f

// ---------------------------------------------------------------------------
// Device scratch (static; no runtime allocation allowed)
// ---------------------------------------------------------------------------
__device__ float g_Zx[(size_t)T_STEPS * B_SZ * NP];  // x-projection for all (t,b): ~1.14 GB
__device__ float g_Z[(size_t)B_SZ * NP];             // per-step pre-activation buffer
__device__ float g_hx[B_SZ * H_SZ];
__device__ float g_cx[B_SZ * H_SZ];
__device__ float g_Wxcat[(size_t)D_SZ * NP];         // packed x-half weights (512 x NP)
__device__ float g_Whcat[(size_t)H_SZ * NP];         // packed h-half weights (512 x NP)

// ---------------------------------------------------------------------------
// Utility kernels
// ---------------------------------------------------------------------------
__global__ void zero_state_kernel() {
    int i = blockIdx.x * blockDim.x + threadIdx.x;
    if (i < B_SZ * H_SZ) { g_hx[i] = 0.0f; g_cx[i] = 0.0f; }
}

// Pack [Wf | Wi | Wu | Wo | Wq | zero-pad] for both the x rows (0..D-1) and
// the h rows (D..D+H-1) of the original (IN, out) row-major weights.
__global__ void pack_weights_kernel(const float* __restrict__ Wf,
                                    const float* __restrict__ Wi,
                                    const float* __restrict__ Wu,
                                    const float* __restrict__ Wo,
                                    const float* __restrict__ Wq) {
    int idx = blockIdx.x * blockDim.x + threadIdx.x;
    const int total = 2 * D_SZ * NP;
    if (idx >= total) return;
    int which = idx / (D_SZ * NP);     // 0 = x-half, 1 = h-half
    int rem   = idx % (D_SZ * NP);
    int k = rem / NP;
    int n = rem % NP;
    int row = which ? (D_SZ + k) : k;  // row in the original (IN=1024) dimension
    float v = 0.0f;
    if (n < 4 * H_SZ) {
        int g = n >> 9;          // /512
        int h = n & (H_SZ - 1);
        const float* W = (g == 0) ? Wf : (g == 1) ? Wi : (g == 2) ? Wu : Wo;
        v = W[(size_t)row * H_SZ + h];
    } else if (n < NCOLS) {
        v = Wq[(size_t)row * NQ + (n - 4 * H_SZ)];
    }
    if (which) g_Whcat[(size_t)k * NP + n] = v;
    else       g_Wxcat[(size_t)k * NP + n] = v;
}

// ---------------------------------------------------------------------------
// Tiled fp32 SGEMM.
// MODE 0: g_Zx[m, :] = A(inputs)[m, :512] @ g_Wxcat          (M = T*B)
// MODE 1: g_Z [m, :] = g_hx[m, :512] @ g_Whcat + g_Zx[t*B+m] (M = B)
// lda = 512 in both modes. N = NP, K = 512. No bounds checks (exact tiling).
// Threads = (BM/TM)*(BN/TN) = 256.
// ---------------------------------------------------------------------------
template <int BM, int BN, int BK, int TM, int TN, int MODE>
__global__ __launch_bounds__(256) void sgemm_kernel(const float* __restrict__ Ain, int t) {
    __shared__ float As[BK][BM];
    __shared__ float Bs[BK][BN];

    const float* __restrict__ A  = (MODE == 0) ? Ain : g_hx;
    const float* __restrict__ Bm = (MODE == 0) ? g_Wxcat : g_Whcat;

    const int tid  = threadIdx.x;
    const int NT   = (BM / TM) * (BN / TN);   // 256
    const int tcol = tid % (BN / TN);
    const int trow = tid / (BN / TN);
    const int m0 = blockIdx.y * BM;
    const int n0 = blockIdx.x * BN;

    float acc[TM][TN];
#pragma unroll
    for (int i = 0; i < TM; i++)
#pragma unroll
        for (int j = 0; j < TN; j++) acc[i][j] = 0.0f;

    const int K = 512;
    for (int k0 = 0; k0 < K; k0 += BK) {
        // Load A tile (BM x BK), store transposed into As[k][m]
#pragma unroll
        for (int i = tid; i < BM * BK / 4; i += NT) {
            int r  = i / (BK / 4);
            int c4 = i % (BK / 4);
            float4 v = *reinterpret_cast<const float4*>(
                &A[(size_t)(m0 + r) * 512 + k0 + c4 * 4]);
            As[c4 * 4 + 0][r] = v.x;
            As[c4 * 4 + 1][r] = v.y;
            As[c4 * 4 + 2][r] = v.z;
            As[c4 * 4 + 3][r] = v.w;
        }
        // Load B tile (BK x BN) row-major
#pragma unroll
        for (int i = tid; i < BK * BN / 4; i += NT) {
            int r  = i / (BN / 4);
            int c4 = i % (BN / 4);
            *reinterpret_cast<float4*>(&Bs[r][c4 * 4]) =
                *reinterpret_cast<const float4*>(&Bm[(size_t)(k0 + r) * NP + n0 + c4 * 4]);
        }
        __syncthreads();

#pragma unroll
        for (int kk = 0; kk < BK; kk++) {
            float a[TM], b[TN];
#pragma unroll
            for (int i = 0; i < TM; i += 4) {
                float4 v = *reinterpret_cast<const float4*>(&As[kk][trow * TM + i]);
                a[i] = v.x; a[i + 1] = v.y; a[i + 2] = v.z; a[i + 3] = v.w;
            }
#pragma unroll
            for (int j = 0; j < TN; j += 4) {
                float4 v = *reinterpret_cast<const float4*>(&Bs[kk][tcol * TN + j]);
                b[j] = v.x; b[j + 1] = v.y; b[j + 2] = v.z; b[j + 3] = v.w;
            }
#pragma unroll
            for (int i = 0; i < TM; i++)
#pragma unroll
                for (int j = 0; j < TN; j++)
                    acc[i][j] = fmaf(a[i], b[j], acc[i][j]);
        }
        __syncthreads();
    }

    // Epilogue
#pragma unroll
    for (int i = 0; i < TM; i++) {
        int m = m0 + trow * TM + i;
#pragma unroll
        for (int j = 0; j < TN; j += 4) {
            size_t off = (size_t)m * NP + n0 + tcol * TN + j;
            float4 v;
            v.x = acc[i][j]; v.y = acc[i][j + 1]; v.z = acc[i][j + 2]; v.w = acc[i][j + 3];
            if (MODE == 0) {
                *reinterpret_cast<float4*>(&g_Zx[off]) = v;
            } else {
                float4 ad = *reinterpret_cast<const float4*>(
                    &g_Zx[(size_t)(t * B_SZ) * NP + off]);
                v.x += ad.x; v.y += ad.y; v.z += ad.z; v.w += ad.w;
                *reinterpret_cast<float4*>(&g_Z[off]) = v;
            }
        }
    }
}

// ---------------------------------------------------------------------------
// Per-step fused update: quantum feature map + 8->512 matvec + gates + state.
// grid = (H/256, B), block = 256.
// ---------------------------------------------------------------------------
__device__ __forceinline__ float sigm(float x) { return 1.0f / (1.0f + expf(-x)); }

__global__ __launch_bounds__(256) void step_update_kernel(
    const float* __restrict__ bf, const float* __restrict__ bi,
    const float* __restrict__ bu, const float* __restrict__ bo,
    const float* __restrict__ bq, const float* __restrict__ Wqh,
    const float* __restrict__ bqh,
    const float* __restrict__ th_f, const float* __restrict__ th_i,
    const float* __restrict__ th_u, const float* __restrict__ th_o,
    float* __restrict__ out, int t) {
    const int b = blockIdx.y;
    const int h = blockIdx.x * blockDim.x + threadIdx.x;
    const size_t zb = (size_t)b * NP;

    // q_in (8 values, broadcast across the block)
    float q[NQ];
#pragma unroll
    for (int j = 0; j < NQ; j++) q[j] = g_Z[zb + 4 * H_SZ + j] + bq[j];

    // cumprod-of-cos feature maps and their 8->H projection (fused)
    float ef = 1.0f, ei = 1.0f, eu = 1.0f, eo = 1.0f;
    float qb = bqh[h];
    float sf = qb, si = qb, su = qb, so = qb;
#pragma unroll
    for (int j = 0; j < NQ; j++) {
        ef *= cosf(q[j] + th_f[j]);
        ei *= cosf(q[j] + th_i[j]);
        eu *= cosf(q[j] + th_u[j]);
        eo *= cosf(q[j] + th_o[j]);
        float w = Wqh[j * H_SZ + h];
        sf = fmaf(ef, w, sf);
        si = fmaf(ei, w, si);
        su = fmaf(eu, w, su);
        so = fmaf(eo, w, so);
    }

    float zf = g_Z[zb + 0 * H_SZ + h] + bf[h];
    float zi = g_Z[zb + 1 * H_SZ + h] + bi[h];
    float zu = g_Z[zb + 2 * H_SZ + h] + bu[h];
    float zo = g_Z[zb + 3 * H_SZ + h] + bo[h];

    float f = ALPHA * sigm(zf) + (1.0f - ALPHA) * sigm(sf);
    float i_ = ALPHA * sigm(zi) + (1.0f - ALPHA) * sigm(si);
    float g = ALPHA * tanhf(zu) + (1.0f - ALPHA) * tanhf(su);
    float o = ALPHA * sigm(zo) + (1.0f - ALPHA) * sigm(so);

    int idx = b * H_SZ + h;
    float c = f * g_cx[idx] + i_ * g;
    float hx = o * tanhf(c);
    g_cx[idx] = c;
    g_hx[idx] = hx;
    out[(size_t)t * B_SZ * H_SZ + idx] = hx;
}

// Write final (hx, cx) to the tail of d_out if the flattened output includes them.
__global__ void write_tail_kernel(float* __restrict__ dst, int count) {
    int i = blockIdx.x * blockDim.x + threadIdx.x;
    if (i < count) {
        dst[i] = (i < B_SZ * H_SZ) ? g_hx[i] : g_cx[i - B_SZ * H_SZ];
    }
}

// ---------------------------------------------------------------------------
// Launch
// ---------------------------------------------------------------------------
extern "C" void kernel_launch(void* const* d_in, const int* in_sizes, int n_in,
                              void* d_out, int out_size) {
    const float* inputs = (const float*)d_in[0];
    const float* Wf = (const float*)d_in[1];  const float* bf = (const float*)d_in[2];
    const float* Wi = (const float*)d_in[3];  const float* bi = (const float*)d_in[4];
    const float* Wu = (const float*)d_in[5];  const float* bu = (const float*)d_in[6];
    const float* Wo = (const float*)d_in[7];  const float* bo = (const float*)d_in[8];
    const float* Wq = (const float*)d_in[9];  const float* bq = (const float*)d_in[10];
    const float* Wqh = (const float*)d_in[11]; const float* bqh = (const float*)d_in[12];
    const float* thf = (const float*)d_in[13]; const float* thi = (const float*)d_in[14];
    const float* thu = (const float*)d_in[15]; const float* tho = (const float*)d_in[16];
    float* out = (float*)d_out;

    // Init state + pack weights (cheap, runs every call for determinism)
    zero_state_kernel<<<(B_SZ * H_SZ + 255) / 256, 256>>>();
    pack_weights_kernel<<<(2 * D_SZ * NP + 255) / 256, 256>>>(Wf, Wi, Wu, Wo, Wq);

    // Precompute x-projection for all timesteps: (T*B, 512) @ (512, NP)
    sgemm_kernel<128, 128, 16, 8, 8, 0>
        <<<dim3(NP / 128, (T_STEPS * B_SZ) / 128), 256>>>(inputs, 0);

    // Sequential recurrence
    for (int t = 0; t < T_STEPS; t++) {
        sgemm_kernel<64, 128, 16, 4, 8, 1>
            <<<dim3(NP / 128, B_SZ / 64), 256>>>(nullptr, t);
        step_update_kernel<<<dim3(H_SZ / 256, B_SZ), 256>>>(
            bf, bi, bu, bo, bq, Wqh, bqh, thf, thi, thu, tho, out, t);
    }

    // Optional tail: final (hx, cx) after the main (T,B,H) output
    long long mainN = (long long)T_STEPS * B_SZ * H_SZ;
    if ((long long)out_size > mainN) {
        long long rem = (long long)out_size - mainN;
        long long cap = (long long)2 * B_SZ * H_SZ;
        int cnt = (int)(rem < cap ? rem : cap);
        write_tail_kernel<<<(cnt + 255) / 256, 256>>>(out + mainN, cnt);
    }
}

// round 14
// speedup vs baseline: 1.0031x; 1.0007x over previous
#include <cuda_runtime.h>
#include <math.h>

// Problem constants
#define T_STEPS 256
#define B_SZ    512
#define D_SZ    512
#define H_SZ    512
#define NQ      8
#define NCOLS   (4 * H_SZ + NQ)   // 2056 real columns
#define NP      2176              // padded to multiple of 128
#define ALPHA   0.7f

// ---------------------------------------------------------------------------
// Device scratch (static; no runtime allocation allowed)
// ---------------------------------------------------------------------------
__device__ float g_Zx[(size_t)T_STEPS * B_SZ * NP];  // x-projection for all (t,b): ~1.14 GB
__device__ float g_Z[(size_t)B_SZ * NP];             // per-step pre-activation buffer
__device__ float g_hx[B_SZ * H_SZ];
__device__ float g_cx[B_SZ * H_SZ];
__device__ float g_Wxcat[(size_t)D_SZ * NP];         // packed x-half weights (512 x NP)
__device__ float g_Whcat[(size_t)H_SZ * NP];         // packed h-half weights (512 x NP)

// ---------------------------------------------------------------------------
// Utility kernels
// ---------------------------------------------------------------------------
__global__ void zero_state_kernel() {
    int i = blockIdx.x * blockDim.x + threadIdx.x;
    if (i < B_SZ * H_SZ) { g_hx[i] = 0.0f; g_cx[i] = 0.0f; }
}

// Pack [Wf | Wi | Wu | Wo | Wq | zero-pad] for both the x rows (0..D-1) and
// the h rows (D..D+H-1) of the original (IN, out) row-major weights.
__global__ void pack_weights_kernel(const float* __restrict__ Wf,
                                    const float* __restrict__ Wi,
                                    const float* __restrict__ Wu,
                                    const float* __restrict__ Wo,
                                    const float* __restrict__ Wq) {
    int idx = blockIdx.x * blockDim.x + threadIdx.x;
    const int total = 2 * D_SZ * NP;
    if (idx >= total) return;
    int which = idx / (D_SZ * NP);     // 0 = x-half, 1 = h-half
    int rem   = idx % (D_SZ * NP);
    int k = rem / NP;
    int n = rem % NP;
    int row = which ? (D_SZ + k) : k;  // row in the original (IN=1024) dimension
    float v = 0.0f;
    if (n < 4 * H_SZ) {
        int g = n >> 9;          // /512
        int h = n & (H_SZ - 1);
        const float* W = (g == 0) ? Wf : (g == 1) ? Wi : (g == 2) ? Wu : Wo;
        v = W[(size_t)row * H_SZ + h];
    } else if (n < NCOLS) {
        v = Wq[(size_t)row * NQ + (n - 4 * H_SZ)];
    }
    if (which) g_Whcat[(size_t)k * NP + n] = v;
    else       g_Wxcat[(size_t)k * NP + n] = v;
}

// ---------------------------------------------------------------------------
// Tiled fp32 SGEMM.
// MODE 0: g_Zx[m, :] = A(inputs)[m, :512] @ g_Wxcat          (M = T*B)
// MODE 1: g_Z [m, :] = g_hx[m, :512] @ g_Whcat + g_Zx[t*B+m] (M = B)
// lda = 512 in both modes. N = NP, K = 512. No bounds checks (exact tiling).
// Threads = (BM/TM)*(BN/TN) = 256.
// ---------------------------------------------------------------------------
template <int BM, int BN, int BK, int TM, int TN, int MODE>
__global__ __launch_bounds__(256) void sgemm_kernel(const float* __restrict__ Ain, int t) {
    __shared__ float As[BK][BM];
    __shared__ float Bs[BK][BN];

    const float* __restrict__ A  = (MODE == 0) ? Ain : g_hx;
    const float* __restrict__ Bm = (MODE == 0) ? g_Wxcat : g_Whcat;

    const int tid  = threadIdx.x;
    const int NT   = (BM / TM) * (BN / TN);   // 256
    const int tcol = tid % (BN / TN);
    const int trow = tid / (BN / TN);
    const int m0 = blockIdx.y * BM;
    const int n0 = blockIdx.x * BN;

    float acc[TM][TN];
#pragma unroll
    for (int i = 0; i < TM; i++)
#pragma unroll
        for (int j = 0; j < TN; j++) acc[i][j] = 0.0f;

    const int K = 512;
    for (int k0 = 0; k0 < K; k0 += BK) {
        // Load A tile (BM x BK), store transposed into As[k][m]
#pragma unroll
        for (int i = tid; i < BM * BK / 4; i += NT) {
            int r  = i / (BK / 4);
            int c4 = i % (BK / 4);
            float4 v = *reinterpret_cast<const float4*>(
                &A[(size_t)(m0 + r) * 512 + k0 + c4 * 4]);
            As[c4 * 4 + 0][r] = v.x;
            As[c4 * 4 + 1][r] = v.y;
            As[c4 * 4 + 2][r] = v.z;
            As[c4 * 4 + 3][r] = v.w;
        }
        // Load B tile (BK x BN) row-major
#pragma unroll
        for (int i = tid; i < BK * BN / 4; i += NT) {
            int r  = i / (BN / 4);
            int c4 = i % (BN / 4);
            *reinterpret_cast<float4*>(&Bs[r][c4 * 4]) =
                *reinterpret_cast<const float4*>(&Bm[(size_t)(k0 + r) * NP + n0 + c4 * 4]);
        }
        __syncthreads();

#pragma unroll
        for (int kk = 0; kk < BK; kk++) {
            float a[TM], b[TN];
#pragma unroll
            for (int i = 0; i < TM; i += 4) {
                float4 v = *reinterpret_cast<const float4*>(&As[kk][trow * TM + i]);
                a[i] = v.x; a[i + 1] = v.y; a[i + 2] = v.z; a[i + 3] = v.w;
            }
#pragma unroll
            for (int j = 0; j < TN; j += 4) {
                float4 v = *reinterpret_cast<const float4*>(&Bs[kk][tcol * TN + j]);
                b[j] = v.x; b[j + 1] = v.y; b[j + 2] = v.z; b[j + 3] = v.w;
            }
#pragma unroll
            for (int i = 0; i < TM; i++)
#pragma unroll
                for (int j = 0; j < TN; j++)
                    acc[i][j] = fmaf(a[i], b[j], acc[i][j]);
        }
        __syncthreads();
    }

    // Epilogue
#pragma unroll
    for (int i = 0; i < TM; i++) {
        int m = m0 + trow * TM + i;
#pragma unroll
        for (int j = 0; j < TN; j += 4) {
            size_t off = (size_t)m * NP + n0 + tcol * TN + j;
            float4 v;
            v.x = acc[i][j]; v.y = acc[i][j + 1]; v.z = acc[i][j + 2]; v.w = acc[i][j + 3];
            if (MODE == 0) {
                *reinterpret_cast<float4*>(&g_Zx[off]) = v;
            } else {
                float4 ad = *reinterpret_cast<const float4*>(
                    &g_Zx[(size_t)(t * B_SZ) * NP + off]);
                v.x += ad.x; v.y += ad.y; v.z += ad.z; v.w += ad.w;
                *reinterpret_cast<float4*>(&g_Z[off]) = v;
            }
        }
    }
}

// ---------------------------------------------------------------------------
// Per-step fused update: quantum feature map + 8->512 matvec + gates + state.
// grid = (H/256, B), block = 256.
// ---------------------------------------------------------------------------
__device__ __forceinline__ float sigm(float x) { return 1.0f / (1.0f + expf(-x)); }

__global__ __launch_bounds__(256) void step_update_kernel(
    const float* __restrict__ bf, const float* __restrict__ bi,
    const float* __restrict__ bu, const float* __restrict__ bo,
    const float* __restrict__ bq, const float* __restrict__ Wqh,
    const float* __restrict__ bqh,
    const float* __restrict__ th_f, const float* __restrict__ th_i,
    const float* __restrict__ th_u, const float* __restrict__ th_o,
    float* __restrict__ out, int t) {
    const int b = blockIdx.y;
    const int h = blockIdx.x * blockDim.x + threadIdx.x;
    const size_t zb = (size_t)b * NP;

    // q_in (8 values, broadcast across the block)
    float q[NQ];
#pragma unroll
    for (int j = 0; j < NQ; j++) q[j] = g_Z[zb + 4 * H_SZ + j] + bq[j];

    // cumprod-of-cos feature maps and their 8->H projection (fused)
    float ef = 1.0f, ei = 1.0f, eu = 1.0f, eo = 1.0f;
    float qb = bqh[h];
    float sf = qb, si = qb, su = qb, so = qb;
#pragma unroll
    for (int j = 0; j < NQ; j++) {
        ef *= cosf(q[j] + th_f[j]);
        ei *= cosf(q[j] + th_i[j]);
        eu *= cosf(q[j] + th_u[j]);
        eo *= cosf(q[j] + th_o[j]);
        float w = Wqh[j * H_SZ + h];
        sf = fmaf(ef, w, sf);
        si = fmaf(ei, w, si);
        su = fmaf(eu, w, su);
        so = fmaf(eo, w, so);
    }

    float zf = g_Z[zb + 0 * H_SZ + h] + bf[h];
    float zi = g_Z[zb + 1 * H_SZ + h] + bi[h];
    float zu = g_Z[zb + 2 * H_SZ + h] + bu[h];
    float zo = g_Z[zb + 3 * H_SZ + h] + bo[h];

    float f = ALPHA * sigm(zf) + (1.0f - ALPHA) * sigm(sf);
    float i_ = ALPHA * sigm(zi) + (1.0f - ALPHA) * sigm(si);
    float g = ALPHA * tanhf(zu) + (1.0f - ALPHA) * tanhf(su);
    float o = ALPHA * sigm(zo) + (1.0f - ALPHA) * sigm(so);

    int idx = b * H_SZ + h;
    float c = f * g_cx[idx] + i_ * g;
    float hx = o * tanhf(c);
    g_cx[idx] = c;
    g_hx[idx] = hx;
    out[(size_t)t * B_SZ * H_SZ + idx] = hx;
}

// Write final (hx, cx) to the tail of d_out if the flattened output includes them.
__global__ void write_tail_kernel(float* __restrict__ dst, int count) {
    int i = blockIdx.x * blockDim.x + threadIdx.x;
    if (i < count) {
        dst[i] = (i < B_SZ * H_SZ) ? g_hx[i] : g_cx[i - B_SZ * H_SZ];
    }
}

// ---------------------------------------------------------------------------
// Launch
// ---------------------------------------------------------------------------
extern "C" void kernel_launch(void* const* d_in, const int* in_sizes, int n_in,
                              void* d_out, int out_size) {
    const float* inputs = (const float*)d_in[0];
    const float* Wf = (const float*)d_in[1];  const float* bf = (const float*)d_in[2];
    const float* Wi = (const float*)d_in[3];  const float* bi = (const float*)d_in[4];
    const float* Wu = (const float*)d_in[5];  const float* bu = (const float*)d_in[6];
    const float* Wo = (const float*)d_in[7];  const float* bo = (const float*)d_in[8];
    const float* Wq = (const float*)d_in[9];  const float* bq = (const float*)d_in[10];
    const float* Wqh = (const float*)d_in[11]; const float* bqh = (const float*)d_in[12];
    const float* thf = (const float*)d_in[13]; const float* thi = (const float*)d_in[14];
    const float* thu = (const float*)d_in[15]; const float* tho = (const float*)d_in[16];
    float* out = (float*)d_out;

    // Init state + pack weights (cheap, runs every call for determinism)
    zero_state_kernel<<<(B_SZ * H_SZ + 255) / 256, 256>>>();
    pack_weights_kernel<<<(2 * D_SZ * NP + 255) / 256, 256>>>(Wf, Wi, Wu, Wo, Wq);

    // Precompute x-projection for all timesteps: (T*B, 512) @ (512, NP)
    sgemm_kernel<128, 128, 16, 8, 8, 0>
        <<<dim3(NP / 128, (T_STEPS * B_SZ) / 128), 256>>>(inputs, 0);

    // Sequential recurrence
    for (int t = 0; t < T_STEPS; t++) {
        sgemm_kernel<64, 128, 16, 4, 8, 1>
            <<<dim3(NP / 128, B_SZ / 64), 256>>>(nullptr, t);
        step_update_kernel<<<dim3(H_SZ / 256, B_SZ), 256>>>(
            bf, bi, bu, bo, bq, Wqh, bqh, thf, thi, thu, tho, out, t);
    }

    // Optional tail: final (hx, cx) after the main (T,B,H) output
    long long mainN = (long long)T_STEPS * B_SZ * H_SZ;
    if ((long long)out_size > mainN) {
        long long rem = (long long)out_size - mainN;
        long long cap = (long long)2 * B_SZ * H_SZ;
        int cnt = (int)(rem < cap ? rem : cap);
        write_tail_kernel<<<(cnt + 255) / 256, 256>>>(out + mainN, cnt);
    }
}